// round 12
// baseline (speedup 1.0000x reference)
#include <cuda_runtime.h>
#include <cuda_bf16.h>
#include <math.h>

#define CNT 262144.0f

__device__ __nv_bfloat16 g_T[4L*64*65536];  // [b][oc][e*1024+j] bf16
__device__ __nv_bfloat16 g_W[4L*64*65536];  // wy bf16
__device__ float g_Gx[4*64*64];
__device__ float g_Gq[4*64*64];
__device__ float g_sx[4*64];
__device__ float g_R[4*64*64];       // R[c][e]
__device__ float g_beta[4*64];
__device__ float g_Sw[64];
__device__ float g_sum[64], g_sumsq[64];

__device__ __forceinline__ unsigned f2tf(float f) {
    unsigned u; asm("cvt.rna.tf32.f32 %0, %1;" : "=r"(u) : "f"(f)); return u;
}
__device__ __forceinline__ float u2f(unsigned u) { return __uint_as_float(u); }
__device__ __forceinline__ void mma8(float* c, const unsigned* a, const unsigned* b) {
    asm("mma.sync.aligned.m16n8k8.row.col.f32.tf32.tf32.f32 "
        "{%0,%1,%2,%3},{%4,%5,%6,%7},{%8,%9},{%0,%1,%2,%3};"
        : "+f"(c[0]), "+f"(c[1]), "+f"(c[2]), "+f"(c[3])
        : "r"(a[0]), "r"(a[1]), "r"(a[2]), "r"(a[3]), "r"(b[0]), "r"(b[1]));
}

__global__ void k0() {
    int i = blockIdx.x * 256 + threadIdx.x;
    if (i < 16384) { g_Gx[i] = 0.f; g_Gq[i] = 0.f; }
    if (i < 256) g_sx[i] = 0.f;
    if (i < 64) { g_sum[i] = 0.f; g_sumsq[i] = 0.f; }
}

// Gram: Gx = Xhi Xhi^T, Gq = Xhi Xlo^T; plus column sums.
__global__ __launch_bounds__(256) void kG(const float* __restrict__ x) {
    extern __shared__ __align__(16) float dsm[];
    float* Xh = dsm;
    float* Xl = dsm + 64 * 132;
    const int b = blockIdx.y, t = threadIdx.x, w = t >> 5, lane = t & 31;
    const int gid = lane >> 2, tig = lane & 3;
    const int rs = w & 3, cg = w >> 2;
    const int cp = t >> 2, q = t & 3;
    float P[4][4], Q[4][4];
#pragma unroll
    for (int u = 0; u < 4; u++)
#pragma unroll
        for (int i = 0; i < 4; i++) { P[u][i] = 0.f; Q[u][i] = 0.f; }
    float sx = 0.f;
    for (int tt = 0; tt < 4; tt++) {
        int n0 = (blockIdx.x * 4 + tt) * 128;
        const float* src = x + ((long)(b * 64 + cp)) * 65536 + n0 + q * 32;
#pragma unroll
        for (int k = 0; k < 8; k++) {
            float4 v = *(const float4*)(src + 4 * k);
            sx += v.x + v.y + v.z + v.w;
            float4 hv = make_float4(u2f(f2tf(v.x)), u2f(f2tf(v.y)),
                                    u2f(f2tf(v.z)), u2f(f2tf(v.w)));
            float4 lv = make_float4(
                u2f(f2tf(v.x - hv.x)), u2f(f2tf(v.y - hv.y)),
                u2f(f2tf(v.z - hv.z)), u2f(f2tf(v.w - hv.w)));
            *(float4*)(Xh + cp * 132 + q * 32 + 4 * k) = hv;
            *(float4*)(Xl + cp * 132 + q * 32 + 4 * k) = lv;
        }
        __syncthreads();
        for (int ks = 0; ks < 16; ks++) {
            const int col = 8 * ks + tig, e0 = rs * 16 + gid;
            unsigned ah[4];
            ah[0] = __float_as_uint(Xh[e0 * 132 + col]);
            ah[1] = __float_as_uint(Xh[(e0 + 8) * 132 + col]);
            ah[2] = __float_as_uint(Xh[e0 * 132 + col + 4]);
            ah[3] = __float_as_uint(Xh[(e0 + 8) * 132 + col + 4]);
#pragma unroll
            for (int u = 0; u < 4; u++) {
                int ep = cg * 32 + 8 * u + gid;
                unsigned bh[2] = {__float_as_uint(Xh[ep * 132 + col]),
                                  __float_as_uint(Xh[ep * 132 + col + 4])};
                unsigned bl[2] = {__float_as_uint(Xl[ep * 132 + col]),
                                  __float_as_uint(Xl[ep * 132 + col + 4])};
                mma8(P[u], ah, bh);
                mma8(Q[u], ah, bl);
            }
        }
        __syncthreads();
    }
    float* Gp = g_Gx + b * 4096;
    float* Gq = g_Gq + b * 4096;
#pragma unroll
    for (int u = 0; u < 4; u++) {
        int r0 = rs * 16 + gid, c0 = cg * 32 + 8 * u + 2 * tig;
        atomicAdd(&Gp[r0 * 64 + c0], P[u][0]);
        atomicAdd(&Gp[r0 * 64 + c0 + 1], P[u][1]);
        atomicAdd(&Gp[(r0 + 8) * 64 + c0], P[u][2]);
        atomicAdd(&Gp[(r0 + 8) * 64 + c0 + 1], P[u][3]);
        atomicAdd(&Gq[r0 * 64 + c0], Q[u][0]);
        atomicAdd(&Gq[r0 * 64 + c0 + 1], Q[u][1]);
        atomicAdd(&Gq[(r0 + 8) * 64 + c0], Q[u][2]);
        atomicAdd(&Gq[(r0 + 8) * 64 + c0 + 1], Q[u][3]);
    }
    sx += __shfl_down_sync(0xffffffffu, sx, 1);
    sx += __shfl_down_sync(0xffffffffu, sx, 2);
    if (q == 0) atomicAdd(&g_sx[b * 64 + cp], sx);
}

// T[b][oc][e*1024+j] = sum_ch Wc[oc][ch] * x[b][e][ch*1024+j]; stored bf16.
__global__ __launch_bounds__(256) void kT(const float* __restrict__ x,
                                          const float* __restrict__ ww) {
    __shared__ __align__(16) float Xs[64 * 132];
    const int be = blockIdx.y;
    const int b = be >> 6, e = be & 63;
    const int t = threadIdx.x, w = t >> 5, lane = t & 31;
    const int gid = lane >> 2, tig = lane & 3;
    const int rs = w & 3, jh = w >> 2;
    const int ch_ld = t >> 2, q = t & 3;
    unsigned aw[8][4];
#pragma unroll
    for (int k = 0; k < 8; k++) {
        int r = rs * 16 + gid, c = 8 * k + tig;
        aw[k][0] = f2tf(ww[r * 64 + c]);
        aw[k][1] = f2tf(ww[(r + 8) * 64 + c]);
        aw[k][2] = f2tf(ww[r * 64 + c + 4]);
        aw[k][3] = f2tf(ww[(r + 8) * 64 + c + 4]);
    }
    const float* xe = x + (long)be * 65536;
    for (int tt = 0; tt < 4; tt++) {
        int j0 = blockIdx.x * 512 + tt * 128;
        const float* src = xe + ch_ld * 1024 + j0 + q * 32;
#pragma unroll
        for (int k = 0; k < 8; k++) {
            float4 v = *(const float4*)(src + 4 * k);
            *(float4*)(Xs + ch_ld * 132 + q * 32 + 4 * k) =
                make_float4(u2f(f2tf(v.x)), u2f(f2tf(v.y)),
                            u2f(f2tf(v.z)), u2f(f2tf(v.w)));
        }
        __syncthreads();
#pragma unroll
        for (int half = 0; half < 2; half++) {
            float acc[4][4];
#pragma unroll
            for (int u = 0; u < 4; u++)
#pragma unroll
                for (int i = 0; i < 4; i++) acc[u][i] = 0.f;
            int nb = jh * 64 + half * 32;
#pragma unroll
            for (int k = 0; k < 8; k++) {
#pragma unroll
                for (int u = 0; u < 4; u++) {
                    int nn = nb + 8 * u + gid;
                    unsigned bh[2] = {__float_as_uint(Xs[(8 * k + tig) * 132 + nn]),
                                      __float_as_uint(Xs[(8 * k + tig + 4) * 132 + nn])};
                    mma8(acc[u], aw[k], bh);
                }
            }
#pragma unroll
            for (int u = 0; u < 4; u++) {
                int oc = rs * 16 + gid, nn = nb + 8 * u + 2 * tig;
                __nv_bfloat16* d0 = g_T + ((long)(b * 64 + oc)) * 65536 + e * 1024 + j0 + nn;
                *(__nv_bfloat162*)d0 = __floats2bfloat162_rn(acc[u][0], acc[u][1]);
                *(__nv_bfloat162*)(d0 + 8L * 65536) = __floats2bfloat162_rn(acc[u][2], acc[u][3]);
            }
        }
        __syncthreads();
    }
}

// f = Pw G Tw^T + rank1, softmax, R, beta, Sw  (G = Gx + Gq + Gq^T)
__global__ __launch_bounds__(1024) void k2(
    const float* __restrict__ tw, const float* __restrict__ tb,
    const float* __restrict__ pw, const float* __restrict__ pb,
    const float* __restrict__ gw, const float* __restrict__ gb,
    const float* __restrict__ ww) {
    __shared__ float A[64 * 68], Bf[64 * 68];
    __shared__ float s_sx[64], s_tsx[64], s_psx[64], s_tb[64], s_pb[64], s_gb[64];
    const int b = blockIdx.x, t = threadIdx.x;
    const int row = t >> 4, col4 = (t & 15) * 4;
    if (t < 64) { s_sx[t] = g_sx[b*64+t]; s_tb[t] = tb[t]; s_pb[t] = pb[t]; s_gb[t] = gb[t]; }
    for (int idx = t; idx < 4096; idx += 1024) A[(idx & 63) * 68 + (idx >> 6)] = tw[idx];
    {
        const float* Gx = g_Gx + b * 4096;
        const float* Gq = g_Gq + b * 4096;
        for (int idx = t; idx < 4096; idx += 1024) {
            int r = idx >> 6, c = idx & 63;
            Bf[r * 68 + c] = Gx[idx] + Gq[idx] + Gq[c * 64 + r];
        }
    }
    __syncthreads();
    if (t < 64) {
        float a1 = 0.f;
#pragma unroll 16
        for (int e = 0; e < 64; e++) a1 += A[e * 68 + t] * s_sx[e];
        s_tsx[t] = a1;
    }
    float acc[4] = {0.f, 0.f, 0.f, 0.f};
#pragma unroll 8
    for (int e = 0; e < 64; e++) {
        float a = Bf[e * 68 + row];
        float4 bv = *(const float4*)(A + e * 68 + col4);
        acc[0] += a * bv.x; acc[1] += a * bv.y; acc[2] += a * bv.z; acc[3] += a * bv.w;
    }
    __syncthreads();
    *(float4*)(Bf + row * 68 + col4) = make_float4(acc[0], acc[1], acc[2], acc[3]);
    for (int idx = t; idx < 4096; idx += 1024) A[(idx & 63) * 68 + (idx >> 6)] = pw[idx];
    __syncthreads();
    if (t < 64) {
        float a2 = 0.f;
#pragma unroll 16
        for (int e = 0; e < 64; e++) a2 += A[e * 68 + t] * s_sx[e];
        s_psx[t] = a2;
    }
    acc[0] = acc[1] = acc[2] = acc[3] = 0.f;
#pragma unroll 8
    for (int e = 0; e < 64; e++) {
        float a = A[e * 68 + row];
        float4 bv = *(const float4*)(Bf + e * 68 + col4);
        acc[0] += a * bv.x; acc[1] += a * bv.y; acc[2] += a * bv.z; acc[3] += a * bv.w;
    }
    __syncthreads();
    {
        int c = row;
#pragma unroll
        for (int j = 0; j < 4; j++) {
            int d = col4 + j;
            Bf[c*68+d] = acc[j] + s_pb[c]*(s_tsx[d] + 65536.f*s_tb[d]) + s_psx[c]*s_tb[d];
        }
    }
    __syncthreads();
    {
        const int w = t >> 5, lane = t & 31;
        for (int c = w*2; c < w*2+2; c++) {
            float v0 = Bf[c*68+lane], v1 = Bf[c*68+32+lane];
            float m = fmaxf(v0, v1);
#pragma unroll
            for (int o = 16; o >= 1; o >>= 1) m = fmaxf(m, __shfl_xor_sync(0xffffffffu, m, o));
            float e0 = __expf(v0-m), e1 = __expf(v1-m), s = e0+e1;
#pragma unroll
            for (int o = 16; o >= 1; o >>= 1) s += __shfl_xor_sync(0xffffffffu, s, o);
            float inv = 1.f/s;
            A[lane*68+c] = e0*inv;
            A[(lane+32)*68+c] = e1*inv;
        }
    }
    __syncthreads();
    for (int idx = t; idx < 4096; idx += 1024) Bf[(idx >> 6) * 68 + (idx & 63)] = gw[idx];
    __syncthreads();
    if (t < 64) {
        float bs = 0.f;
#pragma unroll 16
        for (int d = 0; d < 64; d++) bs += A[d*68+t]*s_gb[d];
        g_beta[b*64+t] = bs;
    }
    acc[0] = acc[1] = acc[2] = acc[3] = 0.f;
#pragma unroll 8
    for (int d = 0; d < 64; d++) {
        float a = A[d * 68 + row];
        float4 bv = *(const float4*)(Bf + d * 68 + col4);
        acc[0] += a * bv.x; acc[1] += a * bv.y; acc[2] += a * bv.z; acc[3] += a * bv.w;
    }
    *(float4*)(g_R + b * 4096 + row * 64 + col4) = make_float4(acc[0], acc[1], acc[2], acc[3]);
    if (b == 0 && t < 64) {
        float s = 0.f;
        const float4* wr = (const float4*)(ww + t * 64);
#pragma unroll
        for (int k = 0; k < 16; k++) {
            float4 v = wr[k];
            s += v.x + v.y + v.z + v.w;
        }
        g_Sw[t] = s;
    }
}

// wy = R*T + bias; write bf16 wy to g_W; accumulate BN stats from fp32 values.
__global__ __launch_bounds__(256) void kB(const float* __restrict__ wbias) {
    __shared__ __align__(16) float As[64 * 72];
    __shared__ __align__(16) float Ds[64 * 68];
    __shared__ float sb[64];
    const int oc = blockIdx.x, b = blockIdx.y, bz = blockIdx.z, t = threadIdx.x;
    const int w = t >> 5, lane = t & 31, gid = lane >> 2, tig = lane & 3;
    const int cs = w & 3, jh = w >> 2;
    if (t < 64) sb[t] = g_beta[b * 64 + t];
    const float swv = g_Sw[oc], wbv = wbias[oc];
    unsigned ar[8][4];
    const float* Rb = g_R + b * 4096;
#pragma unroll
    for (int k = 0; k < 8; k++) {
        int r = cs * 16 + gid, c = 8 * k + tig;
        ar[k][0] = f2tf(Rb[r * 64 + c]);
        ar[k][1] = f2tf(Rb[(r + 8) * 64 + c]);
        ar[k][2] = f2tf(Rb[r * 64 + c + 4]);
        ar[k][3] = f2tf(Rb[(r + 8) * 64 + c + 4]);
    }
    const __nv_bfloat16* Tb = g_T + ((long)(b * 64 + oc)) * 65536;
    __nv_bfloat16* Wb = g_W + ((long)(b * 64 + oc)) * 65536;
    float ls = 0.f, lq = 0.f;
    const int e = t >> 2, q4 = t & 3;
    __syncthreads();
    for (int jt = bz * 2; jt < bz * 2 + 2; jt++) {
        int j0 = jt * 64;
        {
            const uint4* src = (const uint4*)(Tb + e * 1024 + j0 + q4 * 16);
#pragma unroll
            for (int h = 0; h < 2; h++) {
                uint4 r = src[h];
                unsigned vv[4] = {r.x, r.y, r.z, r.w};
#pragma unroll
                for (int m = 0; m < 4; m++) {
                    float2 f = __bfloat1622float2(*(__nv_bfloat162*)&vv[m]);
                    As[e * 72 + q4 * 16 + h * 8 + 2 * m]     = f.x;
                    As[e * 72 + q4 * 16 + h * 8 + 2 * m + 1] = f.y;
                }
            }
        }
        __syncthreads();
#pragma unroll
        for (int nt = 0; nt < 4; nt++) {
            float acc[4] = {0.f, 0.f, 0.f, 0.f};
            int jb = jh * 32 + nt * 8;
#pragma unroll
            for (int k = 0; k < 8; k++) {
                unsigned bh[2] = {__float_as_uint(As[(8 * k + tig) * 72 + jb + gid]),
                                  __float_as_uint(As[(8 * k + tig + 4) * 72 + jb + gid])};
                mma8(acc, ar[k], bh);
            }
            int c0 = cs * 16 + gid, jj = jb + 2 * tig;
            float bias0 = sb[c0] * swv + wbv, bias1 = sb[c0 + 8] * swv + wbv;
            Ds[jj * 68 + c0] = acc[0] + bias0;
            Ds[(jj + 1) * 68 + c0] = acc[1] + bias0;
            Ds[jj * 68 + c0 + 8] = acc[2] + bias1;
            Ds[(jj + 1) * 68 + c0 + 8] = acc[3] + bias1;
        }
        __syncthreads();
        {
            int j = t >> 2, h = t & 3;
#pragma unroll
            for (int kk = 0; kk < 4; kk++) {
                float4 v = *(const float4*)(Ds + j * 68 + h * 16 + 4 * kk);
                ls += v.x + v.y + v.z + v.w;
                lq += v.x * v.x + v.y * v.y + v.z * v.z + v.w * v.w;
                __nv_bfloat162 p0 = __floats2bfloat162_rn(v.x, v.y);
                __nv_bfloat162 p1 = __floats2bfloat162_rn(v.z, v.w);
                uint2 pk;
                pk.x = *(unsigned*)&p0;
                pk.y = *(unsigned*)&p1;
                *(uint2*)(Wb + (j0 + j) * 64 + h * 16 + 4 * kk) = pk;
            }
        }
        __syncthreads();
    }
#pragma unroll
    for (int o = 16; o >= 1; o >>= 1) {
        ls += __shfl_xor_sync(0xffffffffu, ls, o);
        lq += __shfl_xor_sync(0xffffffffu, lq, o);
    }
    if (lane == 0) { atomicAdd(&g_sum[oc], ls); atomicAdd(&g_sumsq[oc], lq); }
}

// BN apply + residual from bf16 wy; scale/shift inline.
__global__ __launch_bounds__(256) void k5(const float* __restrict__ x,
                                          const float* __restrict__ gamma,
                                          const float* __restrict__ bnb,
                                          float* __restrict__ out) {
    long i4 = (long)blockIdx.x * 256 + threadIdx.x;
    int ch = (int)(i4 >> 14) & 63;
    float m = __ldg(&g_sum[ch]) * (1.f / CNT);
    float v = __ldg(&g_sumsq[ch]) * (1.f / CNT) - m * m;
    float sc = __ldg(&gamma[ch]) * rsqrtf(v + 1e-5f);
    float sh = __ldg(&bnb[ch]) - m * sc;
    uint2 wraw = *(const uint2*)(g_W + i4 * 4);
    float2 w0 = __bfloat1622float2(*(__nv_bfloat162*)&wraw.x);
    float2 w1 = __bfloat1622float2(*(__nv_bfloat162*)&wraw.y);
    float4 xv = ((const float4*)x)[i4];
    float4 o;
    o.x = w0.x * sc + sh + xv.x;
    o.y = w0.y * sc + sh + xv.y;
    o.z = w1.x * sc + sh + xv.z;
    o.w = w1.y * sc + sh + xv.w;
    ((float4*)out)[i4] = o;
}

extern "C" void kernel_launch(void* const* d_in, const int* in_sizes, int n_in,
                              void* d_out, int out_size) {
    const float* x  = (const float*)d_in[0];
    const float* tw = (const float*)d_in[1];
    const float* tb = (const float*)d_in[2];
    const float* pw = (const float*)d_in[3];
    const float* pb = (const float*)d_in[4];
    const float* gw = (const float*)d_in[5];
    const float* gb = (const float*)d_in[6];
    const float* ww = (const float*)d_in[7];
    const float* wb = (const float*)d_in[8];
    const float* gamma = (const float*)d_in[9];
    const float* bnb = (const float*)d_in[10];
    float* out = (float*)d_out;

    static cudaStream_t s2 = nullptr;
    static cudaEvent_t evA = nullptr, evB = nullptr;
    if (!s2) {
        cudaStreamCreateWithFlags(&s2, cudaStreamNonBlocking);
        cudaEventCreateWithFlags(&evA, cudaEventDisableTiming);
        cudaEventCreateWithFlags(&evB, cudaEventDisableTiming);
        cudaFuncSetAttribute(kG, cudaFuncAttributeMaxDynamicSharedMemorySize, 70000);
    }
    const int kg_smem = 2 * 64 * 132 * 4;

    // Stream 0: k0 -> kG -> k2 (tiny, 4 blocks)
    // Stream s2: kT starts AFTER kG finishes, so kT (512 blocks) runs
    //            concurrently with k2 and fully hides it.
    k0<<<64, 256>>>();
    kG<<<dim3(128, 4), 256, kg_smem>>>(x);
    cudaEventRecord(evA, 0);
    cudaStreamWaitEvent(s2, evA, 0);
    kT<<<dim3(2, 256), 256, 0, s2>>>(x, ww);
    k2<<<4, 1024>>>(tw, tb, pw, pb, gw, gb, ww);
    cudaEventRecord(evB, s2);
    cudaStreamWaitEvent(0, evB, 0);
    kB<<<dim3(64, 4, 8), 256>>>(wb);
    k5<<<16384, 256>>>(x, gamma, bnb, out);
}

// round 14
// speedup vs baseline: 1.0682x; 1.0682x over previous
#include <cuda_runtime.h>
#include <cuda_bf16.h>
#include <math.h>

#define CNT 262144.0f

__device__ __nv_bfloat16 g_T[4L*64*65536];  // [b][oc][e*1024+j] bf16
__device__ __nv_bfloat16 g_W[4L*64*65536];  // wy bf16
__device__ float g_Gx[4*64*64];
__device__ float g_Gq[4*64*64];
__device__ float g_sx[4*64];
__device__ float g_R[4*64*64];       // R[c][e]
__device__ float g_beta[4*64];
__device__ float g_Sw[64];
__device__ float g_sum[64], g_sumsq[64];

__device__ __forceinline__ unsigned f2tf(float f) {
    unsigned u; asm("cvt.rna.tf32.f32 %0, %1;" : "=r"(u) : "f"(f)); return u;
}
__device__ __forceinline__ float u2f(unsigned u) { return __uint_as_float(u); }
__device__ __forceinline__ void mma8(float* c, const unsigned* a, const unsigned* b) {
    asm("mma.sync.aligned.m16n8k8.row.col.f32.tf32.tf32.f32 "
        "{%0,%1,%2,%3},{%4,%5,%6,%7},{%8,%9},{%0,%1,%2,%3};"
        : "+f"(c[0]), "+f"(c[1]), "+f"(c[2]), "+f"(c[3])
        : "r"(a[0]), "r"(a[1]), "r"(a[2]), "r"(a[3]), "r"(b[0]), "r"(b[1]));
}

__global__ void k0() {
    int i = blockIdx.x * 256 + threadIdx.x;
    if (i < 16384) { g_Gx[i] = 0.f; g_Gq[i] = 0.f; }
    if (i < 256) g_sx[i] = 0.f;
    if (i < 64) { g_sum[i] = 0.f; g_sumsq[i] = 0.f; }
}

// Gram: Gx = Xhi Xhi^T, Gq = Xhi Xlo^T; plus column sums.
__global__ __launch_bounds__(256) void kG(const float* __restrict__ x) {
    extern __shared__ __align__(16) float dsm[];
    float* Xh = dsm;
    float* Xl = dsm + 64 * 132;
    const int b = blockIdx.y, t = threadIdx.x, w = t >> 5, lane = t & 31;
    const int gid = lane >> 2, tig = lane & 3;
    const int rs = w & 3, cg = w >> 2;
    const int cp = t >> 2, q = t & 3;
    float P[4][4], Q[4][4];
#pragma unroll
    for (int u = 0; u < 4; u++)
#pragma unroll
        for (int i = 0; i < 4; i++) { P[u][i] = 0.f; Q[u][i] = 0.f; }
    float sx = 0.f;
    for (int tt = 0; tt < 4; tt++) {
        int n0 = (blockIdx.x * 4 + tt) * 128;
        const float* src = x + ((long)(b * 64 + cp)) * 65536 + n0 + q * 32;
#pragma unroll
        for (int k = 0; k < 8; k++) {
            float4 v = *(const float4*)(src + 4 * k);
            sx += v.x + v.y + v.z + v.w;
            float4 hv = make_float4(u2f(f2tf(v.x)), u2f(f2tf(v.y)),
                                    u2f(f2tf(v.z)), u2f(f2tf(v.w)));
            float4 lv = make_float4(
                u2f(f2tf(v.x - hv.x)), u2f(f2tf(v.y - hv.y)),
                u2f(f2tf(v.z - hv.z)), u2f(f2tf(v.w - hv.w)));
            *(float4*)(Xh + cp * 132 + q * 32 + 4 * k) = hv;
            *(float4*)(Xl + cp * 132 + q * 32 + 4 * k) = lv;
        }
        __syncthreads();
        for (int ks = 0; ks < 16; ks++) {
            const int col = 8 * ks + tig, e0 = rs * 16 + gid;
            unsigned ah[4];
            ah[0] = __float_as_uint(Xh[e0 * 132 + col]);
            ah[1] = __float_as_uint(Xh[(e0 + 8) * 132 + col]);
            ah[2] = __float_as_uint(Xh[e0 * 132 + col + 4]);
            ah[3] = __float_as_uint(Xh[(e0 + 8) * 132 + col + 4]);
#pragma unroll
            for (int u = 0; u < 4; u++) {
                int ep = cg * 32 + 8 * u + gid;
                unsigned bh[2] = {__float_as_uint(Xh[ep * 132 + col]),
                                  __float_as_uint(Xh[ep * 132 + col + 4])};
                unsigned bl[2] = {__float_as_uint(Xl[ep * 132 + col]),
                                  __float_as_uint(Xl[ep * 132 + col + 4])};
                mma8(P[u], ah, bh);
                mma8(Q[u], ah, bl);
            }
        }
        __syncthreads();
    }
    float* Gp = g_Gx + b * 4096;
    float* Gq = g_Gq + b * 4096;
#pragma unroll
    for (int u = 0; u < 4; u++) {
        int r0 = rs * 16 + gid, c0 = cg * 32 + 8 * u + 2 * tig;
        atomicAdd(&Gp[r0 * 64 + c0], P[u][0]);
        atomicAdd(&Gp[r0 * 64 + c0 + 1], P[u][1]);
        atomicAdd(&Gp[(r0 + 8) * 64 + c0], P[u][2]);
        atomicAdd(&Gp[(r0 + 8) * 64 + c0 + 1], P[u][3]);
        atomicAdd(&Gq[r0 * 64 + c0], Q[u][0]);
        atomicAdd(&Gq[r0 * 64 + c0 + 1], Q[u][1]);
        atomicAdd(&Gq[(r0 + 8) * 64 + c0], Q[u][2]);
        atomicAdd(&Gq[(r0 + 8) * 64 + c0 + 1], Q[u][3]);
    }
    sx += __shfl_down_sync(0xffffffffu, sx, 1);
    sx += __shfl_down_sync(0xffffffffu, sx, 2);
    if (q == 0) atomicAdd(&g_sx[b * 64 + cp], sx);
}

// T[b][oc][e*1024+j] = sum_ch Wc[oc][ch] * x[b][e][ch*1024+j]; stored bf16.
__global__ __launch_bounds__(256) void kT(const float* __restrict__ x,
                                          const float* __restrict__ ww) {
    __shared__ __align__(16) float Xs[64 * 132];
    const int be = blockIdx.y;
    const int b = be >> 6, e = be & 63;
    const int t = threadIdx.x, w = t >> 5, lane = t & 31;
    const int gid = lane >> 2, tig = lane & 3;
    const int rs = w & 3, jh = w >> 2;
    const int ch_ld = t >> 2, q = t & 3;
    unsigned aw[8][4];
#pragma unroll
    for (int k = 0; k < 8; k++) {
        int r = rs * 16 + gid, c = 8 * k + tig;
        aw[k][0] = f2tf(ww[r * 64 + c]);
        aw[k][1] = f2tf(ww[(r + 8) * 64 + c]);
        aw[k][2] = f2tf(ww[r * 64 + c + 4]);
        aw[k][3] = f2tf(ww[(r + 8) * 64 + c + 4]);
    }
    const float* xe = x + (long)be * 65536;
    for (int tt = 0; tt < 4; tt++) {
        int j0 = blockIdx.x * 512 + tt * 128;
        const float* src = xe + ch_ld * 1024 + j0 + q * 32;
#pragma unroll
        for (int k = 0; k < 8; k++) {
            float4 v = *(const float4*)(src + 4 * k);
            *(float4*)(Xs + ch_ld * 132 + q * 32 + 4 * k) =
                make_float4(u2f(f2tf(v.x)), u2f(f2tf(v.y)),
                            u2f(f2tf(v.z)), u2f(f2tf(v.w)));
        }
        __syncthreads();
#pragma unroll
        for (int half = 0; half < 2; half++) {
            float acc[4][4];
#pragma unroll
            for (int u = 0; u < 4; u++)
#pragma unroll
                for (int i = 0; i < 4; i++) acc[u][i] = 0.f;
            int nb = jh * 64 + half * 32;
#pragma unroll
            for (int k = 0; k < 8; k++) {
#pragma unroll
                for (int u = 0; u < 4; u++) {
                    int nn = nb + 8 * u + gid;
                    unsigned bh[2] = {__float_as_uint(Xs[(8 * k + tig) * 132 + nn]),
                                      __float_as_uint(Xs[(8 * k + tig + 4) * 132 + nn])};
                    mma8(acc[u], aw[k], bh);
                }
            }
#pragma unroll
            for (int u = 0; u < 4; u++) {
                int oc = rs * 16 + gid, nn = nb + 8 * u + 2 * tig;
                __nv_bfloat16* d0 = g_T + ((long)(b * 64 + oc)) * 65536 + e * 1024 + j0 + nn;
                *(__nv_bfloat162*)d0 = __floats2bfloat162_rn(acc[u][0], acc[u][1]);
                *(__nv_bfloat162*)(d0 + 8L * 65536) = __floats2bfloat162_rn(acc[u][2], acc[u][3]);
            }
        }
        __syncthreads();
    }
}

// f = Pw G Tw^T + rank1, softmax, R, beta, Sw  (G = Gx + Gq + Gq^T)
__global__ __launch_bounds__(1024) void k2(
    const float* __restrict__ tw, const float* __restrict__ tb,
    const float* __restrict__ pw, const float* __restrict__ pb,
    const float* __restrict__ gw, const float* __restrict__ gb,
    const float* __restrict__ ww) {
    __shared__ float A[64 * 68], Bf[64 * 68];
    __shared__ float s_sx[64], s_tsx[64], s_psx[64], s_tb[64], s_pb[64], s_gb[64];
    const int b = blockIdx.x, t = threadIdx.x;
    const int row = t >> 4, col4 = (t & 15) * 4;
    if (t < 64) { s_sx[t] = g_sx[b*64+t]; s_tb[t] = tb[t]; s_pb[t] = pb[t]; s_gb[t] = gb[t]; }
    for (int idx = t; idx < 4096; idx += 1024) A[(idx & 63) * 68 + (idx >> 6)] = tw[idx];
    {
        const float* Gx = g_Gx + b * 4096;
        const float* Gq = g_Gq + b * 4096;
        for (int idx = t; idx < 4096; idx += 1024) {
            int r = idx >> 6, c = idx & 63;
            Bf[r * 68 + c] = Gx[idx] + Gq[idx] + Gq[c * 64 + r];
        }
    }
    __syncthreads();
    if (t < 64) {
        float a1 = 0.f;
#pragma unroll 16
        for (int e = 0; e < 64; e++) a1 += A[e * 68 + t] * s_sx[e];
        s_tsx[t] = a1;
    }
    float acc[4] = {0.f, 0.f, 0.f, 0.f};
#pragma unroll 8
    for (int e = 0; e < 64; e++) {
        float a = Bf[e * 68 + row];
        float4 bv = *(const float4*)(A + e * 68 + col4);
        acc[0] += a * bv.x; acc[1] += a * bv.y; acc[2] += a * bv.z; acc[3] += a * bv.w;
    }
    __syncthreads();
    *(float4*)(Bf + row * 68 + col4) = make_float4(acc[0], acc[1], acc[2], acc[3]);
    for (int idx = t; idx < 4096; idx += 1024) A[(idx & 63) * 68 + (idx >> 6)] = pw[idx];
    __syncthreads();
    if (t < 64) {
        float a2 = 0.f;
#pragma unroll 16
        for (int e = 0; e < 64; e++) a2 += A[e * 68 + t] * s_sx[e];
        s_psx[t] = a2;
    }
    acc[0] = acc[1] = acc[2] = acc[3] = 0.f;
#pragma unroll 8
    for (int e = 0; e < 64; e++) {
        float a = A[e * 68 + row];
        float4 bv = *(const float4*)(Bf + e * 68 + col4);
        acc[0] += a * bv.x; acc[1] += a * bv.y; acc[2] += a * bv.z; acc[3] += a * bv.w;
    }
    __syncthreads();
    {
        int c = row;
#pragma unroll
        for (int j = 0; j < 4; j++) {
            int d = col4 + j;
            Bf[c*68+d] = acc[j] + s_pb[c]*(s_tsx[d] + 65536.f*s_tb[d]) + s_psx[c]*s_tb[d];
        }
    }
    __syncthreads();
    {
        const int w = t >> 5, lane = t & 31;
        for (int c = w*2; c < w*2+2; c++) {
            float v0 = Bf[c*68+lane], v1 = Bf[c*68+32+lane];
            float m = fmaxf(v0, v1);
#pragma unroll
            for (int o = 16; o >= 1; o >>= 1) m = fmaxf(m, __shfl_xor_sync(0xffffffffu, m, o));
            float e0 = __expf(v0-m), e1 = __expf(v1-m), s = e0+e1;
#pragma unroll
            for (int o = 16; o >= 1; o >>= 1) s += __shfl_xor_sync(0xffffffffu, s, o);
            float inv = 1.f/s;
            A[lane*68+c] = e0*inv;
            A[(lane+32)*68+c] = e1*inv;
        }
    }
    __syncthreads();
    for (int idx = t; idx < 4096; idx += 1024) Bf[(idx >> 6) * 68 + (idx & 63)] = gw[idx];
    __syncthreads();
    if (t < 64) {
        float bs = 0.f;
#pragma unroll 16
        for (int d = 0; d < 64; d++) bs += A[d*68+t]*s_gb[d];
        g_beta[b*64+t] = bs;
    }
    acc[0] = acc[1] = acc[2] = acc[3] = 0.f;
#pragma unroll 8
    for (int d = 0; d < 64; d++) {
        float a = A[d * 68 + row];
        float4 bv = *(const float4*)(Bf + d * 68 + col4);
        acc[0] += a * bv.x; acc[1] += a * bv.y; acc[2] += a * bv.z; acc[3] += a * bv.w;
    }
    *(float4*)(g_R + b * 4096 + row * 64 + col4) = make_float4(acc[0], acc[1], acc[2], acc[3]);
    if (b == 0 && t < 64) {
        float s = 0.f;
        const float4* wr = (const float4*)(ww + t * 64);
#pragma unroll
        for (int k = 0; k < 16; k++) {
            float4 v = wr[k];
            s += v.x + v.y + v.z + v.w;
        }
        g_Sw[t] = s;
    }
}

// wy = R*T + bias; write bf16 wy to g_W; accumulate BN stats from fp32 values.
__global__ __launch_bounds__(256) void kB(const float* __restrict__ wbias) {
    __shared__ __align__(16) float As[64 * 72];
    __shared__ __align__(16) float Ds[64 * 68];
    __shared__ float sb[64];
    const int oc = blockIdx.x, b = blockIdx.y, bz = blockIdx.z, t = threadIdx.x;
    const int w = t >> 5, lane = t & 31, gid = lane >> 2, tig = lane & 3;
    const int cs = w & 3, jh = w >> 2;
    if (t < 64) sb[t] = g_beta[b * 64 + t];
    const float swv = g_Sw[oc], wbv = wbias[oc];
    unsigned ar[8][4];
    const float* Rb = g_R + b * 4096;
#pragma unroll
    for (int k = 0; k < 8; k++) {
        int r = cs * 16 + gid, c = 8 * k + tig;
        ar[k][0] = f2tf(Rb[r * 64 + c]);
        ar[k][1] = f2tf(Rb[(r + 8) * 64 + c]);
        ar[k][2] = f2tf(Rb[r * 64 + c + 4]);
        ar[k][3] = f2tf(Rb[(r + 8) * 64 + c + 4]);
    }
    const __nv_bfloat16* Tb = g_T + ((long)(b * 64 + oc)) * 65536;
    __nv_bfloat16* Wb = g_W + ((long)(b * 64 + oc)) * 65536;
    float ls = 0.f, lq = 0.f;
    const int e = t >> 2, q4 = t & 3;
    __syncthreads();
    for (int jt = bz * 4; jt < bz * 4 + 4; jt++) {
        int j0 = jt * 64;
        {
            const uint4* src = (const uint4*)(Tb + e * 1024 + j0 + q4 * 16);
#pragma unroll
            for (int h = 0; h < 2; h++) {
                uint4 r = src[h];
                unsigned vv[4] = {r.x, r.y, r.z, r.w};
#pragma unroll
                for (int m = 0; m < 4; m++) {
                    float2 f = __bfloat1622float2(*(__nv_bfloat162*)&vv[m]);
                    As[e * 72 + q4 * 16 + h * 8 + 2 * m]     = f.x;
                    As[e * 72 + q4 * 16 + h * 8 + 2 * m + 1] = f.y;
                }
            }
        }
        __syncthreads();
#pragma unroll
        for (int nt = 0; nt < 4; nt++) {
            float acc[4] = {0.f, 0.f, 0.f, 0.f};
            int jb = jh * 32 + nt * 8;
#pragma unroll
            for (int k = 0; k < 8; k++) {
                unsigned bh[2] = {__float_as_uint(As[(8 * k + tig) * 72 + jb + gid]),
                                  __float_as_uint(As[(8 * k + tig + 4) * 72 + jb + gid])};
                mma8(acc, ar[k], bh);
            }
            int c0 = cs * 16 + gid, jj = jb + 2 * tig;
            float bias0 = sb[c0] * swv + wbv, bias1 = sb[c0 + 8] * swv + wbv;
            Ds[jj * 68 + c0] = acc[0] + bias0;
            Ds[(jj + 1) * 68 + c0] = acc[1] + bias0;
            Ds[jj * 68 + c0 + 8] = acc[2] + bias1;
            Ds[(jj + 1) * 68 + c0 + 8] = acc[3] + bias1;
        }
        __syncthreads();
        {
            int j = t >> 2, h = t & 3;
#pragma unroll
            for (int kk = 0; kk < 4; kk++) {
                float4 v = *(const float4*)(Ds + j * 68 + h * 16 + 4 * kk);
                ls += v.x + v.y + v.z + v.w;
                lq += v.x * v.x + v.y * v.y + v.z * v.z + v.w * v.w;
                __nv_bfloat162 p0 = __floats2bfloat162_rn(v.x, v.y);
                __nv_bfloat162 p1 = __floats2bfloat162_rn(v.z, v.w);
                uint2 pk;
                pk.x = *(unsigned*)&p0;
                pk.y = *(unsigned*)&p1;
                *(uint2*)(Wb + (j0 + j) * 64 + h * 16 + 4 * kk) = pk;
            }
        }
        __syncthreads();
    }
#pragma unroll
    for (int o = 16; o >= 1; o >>= 1) {
        ls += __shfl_xor_sync(0xffffffffu, ls, o);
        lq += __shfl_xor_sync(0xffffffffu, lq, o);
    }
    if (lane == 0) { atomicAdd(&g_sum[oc], ls); atomicAdd(&g_sumsq[oc], lq); }
}

// BN apply + residual from bf16 wy; scale/shift inline.
__global__ __launch_bounds__(256) void k5(const float* __restrict__ x,
                                          const float* __restrict__ gamma,
                                          const float* __restrict__ bnb,
                                          float* __restrict__ out) {
    long i4 = (long)blockIdx.x * 256 + threadIdx.x;
    int ch = (int)(i4 >> 14) & 63;
    float m = __ldg(&g_sum[ch]) * (1.f / CNT);
    float v = __ldg(&g_sumsq[ch]) * (1.f / CNT) - m * m;
    float sc = __ldg(&gamma[ch]) * rsqrtf(v + 1e-5f);
    float sh = __ldg(&bnb[ch]) - m * sc;
    uint2 wraw = *(const uint2*)(g_W + i4 * 4);
    float2 w0 = __bfloat1622float2(*(__nv_bfloat162*)&wraw.x);
    float2 w1 = __bfloat1622float2(*(__nv_bfloat162*)&wraw.y);
    float4 xv = ((const float4*)x)[i4];
    float4 o;
    o.x = w0.x * sc + sh + xv.x;
    o.y = w0.y * sc + sh + xv.y;
    o.z = w1.x * sc + sh + xv.z;
    o.w = w1.y * sc + sh + xv.w;
    ((float4*)out)[i4] = o;
}

extern "C" void kernel_launch(void* const* d_in, const int* in_sizes, int n_in,
                              void* d_out, int out_size) {
    const float* x  = (const float*)d_in[0];
    const float* tw = (const float*)d_in[1];
    const float* tb = (const float*)d_in[2];
    const float* pw = (const float*)d_in[3];
    const float* pb = (const float*)d_in[4];
    const float* gw = (const float*)d_in[5];
    const float* gb = (const float*)d_in[6];
    const float* ww = (const float*)d_in[7];
    const float* wb = (const float*)d_in[8];
    const float* gamma = (const float*)d_in[9];
    const float* bnb = (const float*)d_in[10];
    float* out = (float*)d_out;

    static cudaStream_t s2 = nullptr;
    static cudaEvent_t evA = nullptr, evB = nullptr;
    if (!s2) {
        int leastPrio = 0, greatestPrio = 0;
        cudaDeviceGetStreamPriorityRange(&leastPrio, &greatestPrio);
        // kT on LOWEST priority: kG wins the timeslice race, finishes early,
        // and k2 then overlaps kT's tail instead of running exposed.
        cudaStreamCreateWithPriority(&s2, cudaStreamNonBlocking, leastPrio);
        cudaEventCreateWithFlags(&evA, cudaEventDisableTiming);
        cudaEventCreateWithFlags(&evB, cudaEventDisableTiming);
        cudaFuncSetAttribute(kG, cudaFuncAttributeMaxDynamicSharedMemorySize, 70000);
    }
    const int kg_smem = 2 * 64 * 132 * 4;

    // Fork at start: kG and kT run concurrently (x shared via L2);
    // kT deprioritized so its tail hides k2.
    k0<<<64, 256>>>();
    cudaEventRecord(evA, 0);
    cudaStreamWaitEvent(s2, evA, 0);
    kT<<<dim3(2, 256), 256, 0, s2>>>(x, ww);
    kG<<<dim3(128, 4), 256, kg_smem>>>(x);
    k2<<<4, 1024>>>(tw, tb, pw, pb, gw, gb, ww);
    cudaEventRecord(evB, s2);
    cudaStreamWaitEvent(0, evB, 0);
    kB<<<dim3(64, 4, 4), 256>>>(wb);
    k5<<<16384, 256>>>(x, gamma, bnb, out);
}

// round 16
// speedup vs baseline: 1.1237x; 1.0519x over previous
#include <cuda_runtime.h>
#include <cuda_bf16.h>
#include <math.h>

#define CNT 262144.0f

__device__ __nv_bfloat16 g_T[4L*64*65536];  // [b][oc][e*1024+j] bf16
__device__ __nv_bfloat16 g_W[4L*64*65536];  // wy bf16
__device__ float g_Gx[4*64*64];
__device__ float g_Gq[4*64*64];
__device__ float g_sx[4*64];
__device__ float g_R[4*64*64];       // R[c][e]
__device__ float g_beta[4*64];
__device__ float g_Sw[64];
__device__ float g_sum[64], g_sumsq[64];

__device__ __forceinline__ unsigned f2tf(float f) {
    unsigned u; asm("cvt.rna.tf32.f32 %0, %1;" : "=r"(u) : "f"(f)); return u;
}
__device__ __forceinline__ float u2f(unsigned u) { return __uint_as_float(u); }
__device__ __forceinline__ unsigned bpk(float a, float b) {
    __nv_bfloat162 t = __floats2bfloat162_rn(a, b);
    return *(unsigned*)&t;
}
__device__ __forceinline__ void mma8(float* c, const unsigned* a, const unsigned* b) {
    asm("mma.sync.aligned.m16n8k8.row.col.f32.tf32.tf32.f32 "
        "{%0,%1,%2,%3},{%4,%5,%6,%7},{%8,%9},{%0,%1,%2,%3};"
        : "+f"(c[0]), "+f"(c[1]), "+f"(c[2]), "+f"(c[3])
        : "r"(a[0]), "r"(a[1]), "r"(a[2]), "r"(a[3]), "r"(b[0]), "r"(b[1]));
}
__device__ __forceinline__ void mma16(float* c, const unsigned* a, const unsigned* b) {
    asm("mma.sync.aligned.m16n8k16.row.col.f32.bf16.bf16.f32 "
        "{%0,%1,%2,%3},{%4,%5,%6,%7},{%8,%9},{%0,%1,%2,%3};"
        : "+f"(c[0]), "+f"(c[1]), "+f"(c[2]), "+f"(c[3])
        : "r"(a[0]), "r"(a[1]), "r"(a[2]), "r"(a[3]), "r"(b[0]), "r"(b[1]));
}

__global__ void k0() {
    int i = blockIdx.x * 256 + threadIdx.x;
    if (i < 16384) { g_Gx[i] = 0.f; g_Gq[i] = 0.f; }
    if (i < 256) g_sx[i] = 0.f;
    if (i < 64) { g_sum[i] = 0.f; g_sumsq[i] = 0.f; }
}

// Gram: Gx = Xhi Xhi^T, Gq = Xhi Xlo^T (3xTF32); plus column sums.
__global__ __launch_bounds__(256) void kG(const float* __restrict__ x) {
    extern __shared__ __align__(16) float dsm[];
    float* Xh = dsm;
    float* Xl = dsm + 64 * 132;
    const int b = blockIdx.y, t = threadIdx.x, w = t >> 5, lane = t & 31;
    const int gid = lane >> 2, tig = lane & 3;
    const int rs = w & 3, cg = w >> 2;
    const int cp = t >> 2, q = t & 3;
    float P[4][4], Q[4][4];
#pragma unroll
    for (int u = 0; u < 4; u++)
#pragma unroll
        for (int i = 0; i < 4; i++) { P[u][i] = 0.f; Q[u][i] = 0.f; }
    float sx = 0.f;
    for (int tt = 0; tt < 4; tt++) {
        int n0 = (blockIdx.x * 4 + tt) * 128;
        const float* src = x + ((long)(b * 64 + cp)) * 65536 + n0 + q * 32;
#pragma unroll
        for (int k = 0; k < 8; k++) {
            float4 v = *(const float4*)(src + 4 * k);
            sx += v.x + v.y + v.z + v.w;
            float4 hv = make_float4(u2f(f2tf(v.x)), u2f(f2tf(v.y)),
                                    u2f(f2tf(v.z)), u2f(f2tf(v.w)));
            float4 lv = make_float4(
                u2f(f2tf(v.x - hv.x)), u2f(f2tf(v.y - hv.y)),
                u2f(f2tf(v.z - hv.z)), u2f(f2tf(v.w - hv.w)));
            *(float4*)(Xh + cp * 132 + q * 32 + 4 * k) = hv;
            *(float4*)(Xl + cp * 132 + q * 32 + 4 * k) = lv;
        }
        __syncthreads();
        for (int ks = 0; ks < 16; ks++) {
            const int col = 8 * ks + tig, e0 = rs * 16 + gid;
            unsigned ah[4];
            ah[0] = __float_as_uint(Xh[e0 * 132 + col]);
            ah[1] = __float_as_uint(Xh[(e0 + 8) * 132 + col]);
            ah[2] = __float_as_uint(Xh[e0 * 132 + col + 4]);
            ah[3] = __float_as_uint(Xh[(e0 + 8) * 132 + col + 4]);
#pragma unroll
            for (int u = 0; u < 4; u++) {
                int ep = cg * 32 + 8 * u + gid;
                unsigned bh[2] = {__float_as_uint(Xh[ep * 132 + col]),
                                  __float_as_uint(Xh[ep * 132 + col + 4])};
                unsigned bl[2] = {__float_as_uint(Xl[ep * 132 + col]),
                                  __float_as_uint(Xl[ep * 132 + col + 4])};
                mma8(P[u], ah, bh);
                mma8(Q[u], ah, bl);
            }
        }
        __syncthreads();
    }
    float* Gp = g_Gx + b * 4096;
    float* Gq = g_Gq + b * 4096;
#pragma unroll
    for (int u = 0; u < 4; u++) {
        int r0 = rs * 16 + gid, c0 = cg * 32 + 8 * u + 2 * tig;
        atomicAdd(&Gp[r0 * 64 + c0], P[u][0]);
        atomicAdd(&Gp[r0 * 64 + c0 + 1], P[u][1]);
        atomicAdd(&Gp[(r0 + 8) * 64 + c0], P[u][2]);
        atomicAdd(&Gp[(r0 + 8) * 64 + c0 + 1], P[u][3]);
        atomicAdd(&Gq[r0 * 64 + c0], Q[u][0]);
        atomicAdd(&Gq[r0 * 64 + c0 + 1], Q[u][1]);
        atomicAdd(&Gq[(r0 + 8) * 64 + c0], Q[u][2]);
        atomicAdd(&Gq[(r0 + 8) * 64 + c0 + 1], Q[u][3]);
    }
    sx += __shfl_down_sync(0xffffffffu, sx, 1);
    sx += __shfl_down_sync(0xffffffffu, sx, 2);
    if (q == 0) atomicAdd(&g_sx[b * 64 + cp], sx);
}

// T[b][oc][e*1024+j] = sum_ch Wc[oc][ch] * x[b][e][ch*1024+j]
// bf16 m16n8k16 MMA: half the mma instruction count vs tf32 k8.
__global__ __launch_bounds__(256) void kT(const float* __restrict__ x,
                                          const float* __restrict__ ww) {
    __shared__ __align__(16) __nv_bfloat16 Xs[64 * 136];
    const int be = blockIdx.y;
    const int b = be >> 6, e = be & 63;
    const int t = threadIdx.x, w = t >> 5, lane = t & 31;
    const int gid = lane >> 2, tig = lane & 3;
    const int rs = w & 3, jh = w >> 2;
    const int ch_ld = t >> 2, q = t & 3;
    const int r = rs * 16 + gid;
    unsigned aw[4][4];
#pragma unroll
    for (int s = 0; s < 4; s++) {
        int c = 16 * s + 2 * tig;
        aw[s][0] = bpk(ww[r * 64 + c],           ww[r * 64 + c + 1]);
        aw[s][1] = bpk(ww[(r + 8) * 64 + c],     ww[(r + 8) * 64 + c + 1]);
        aw[s][2] = bpk(ww[r * 64 + c + 8],       ww[r * 64 + c + 9]);
        aw[s][3] = bpk(ww[(r + 8) * 64 + c + 8], ww[(r + 8) * 64 + c + 9]);
    }
    const float* xe = x + (long)be * 65536;
    const unsigned short* Xu = (const unsigned short*)Xs;
    for (int tt = 0; tt < 4; tt++) {
        int j0 = blockIdx.x * 512 + tt * 128;
        const float* src = xe + ch_ld * 1024 + j0 + q * 32;
#pragma unroll
        for (int k = 0; k < 8; k++) {
            float4 v = *(const float4*)(src + 4 * k);
            uint2 pp;
            pp.x = bpk(v.x, v.y);
            pp.y = bpk(v.z, v.w);
            *(uint2*)(Xs + ch_ld * 136 + q * 32 + 4 * k) = pp;
        }
        __syncthreads();
#pragma unroll
        for (int hf = 0; hf < 2; hf++) {
            float acc[4][4];
#pragma unroll
            for (int u = 0; u < 4; u++)
#pragma unroll
                for (int i = 0; i < 4; i++) acc[u][i] = 0.f;
            int nb = jh * 64 + hf * 32;
#pragma unroll
            for (int s = 0; s < 4; s++) {
                int r0 = 16 * s + 2 * tig;
#pragma unroll
                for (int u = 0; u < 4; u++) {
                    int nn = nb + 8 * u + gid;
                    unsigned bb[2];
                    bb[0] = (unsigned)Xu[r0 * 136 + nn] |
                            ((unsigned)Xu[(r0 + 1) * 136 + nn] << 16);
                    bb[1] = (unsigned)Xu[(r0 + 8) * 136 + nn] |
                            ((unsigned)Xu[(r0 + 9) * 136 + nn] << 16);
                    mma16(acc[u], aw[s], bb);
                }
            }
#pragma unroll
            for (int u = 0; u < 4; u++) {
                int oc = rs * 16 + gid, nn = nb + 8 * u + 2 * tig;
                __nv_bfloat16* d0 = g_T + ((long)(b * 64 + oc)) * 65536 + e * 1024 + j0 + nn;
                *(__nv_bfloat162*)d0 = __floats2bfloat162_rn(acc[u][0], acc[u][1]);
                *(__nv_bfloat162*)(d0 + 8L * 65536) = __floats2bfloat162_rn(acc[u][2], acc[u][3]);
            }
        }
        __syncthreads();
    }
}

// f = Pw G Tw^T + rank1, softmax, R, beta, Sw  (G = Gx + Gq + Gq^T)
__global__ __launch_bounds__(1024) void k2(
    const float* __restrict__ tw, const float* __restrict__ tb,
    const float* __restrict__ pw, const float* __restrict__ pb,
    const float* __restrict__ gw, const float* __restrict__ gb,
    const float* __restrict__ ww) {
    __shared__ float A[64 * 68], Bf[64 * 68];
    __shared__ float s_sx[64], s_tsx[64], s_psx[64], s_tb[64], s_pb[64], s_gb[64];
    const int b = blockIdx.x, t = threadIdx.x;
    const int row = t >> 4, col4 = (t & 15) * 4;
    if (t < 64) { s_sx[t] = g_sx[b*64+t]; s_tb[t] = tb[t]; s_pb[t] = pb[t]; s_gb[t] = gb[t]; }
    for (int idx = t; idx < 4096; idx += 1024) A[(idx & 63) * 68 + (idx >> 6)] = tw[idx];
    {
        const float* Gx = g_Gx + b * 4096;
        const float* Gq = g_Gq + b * 4096;
        for (int idx = t; idx < 4096; idx += 1024) {
            int r = idx >> 6, c = idx & 63;
            Bf[r * 68 + c] = Gx[idx] + Gq[idx] + Gq[c * 64 + r];
        }
    }
    __syncthreads();
    if (t < 64) {
        float a1 = 0.f;
#pragma unroll 16
        for (int e = 0; e < 64; e++) a1 += A[e * 68 + t] * s_sx[e];
        s_tsx[t] = a1;
    }
    float acc[4] = {0.f, 0.f, 0.f, 0.f};
#pragma unroll 8
    for (int e = 0; e < 64; e++) {
        float a = Bf[e * 68 + row];
        float4 bv = *(const float4*)(A + e * 68 + col4);
        acc[0] += a * bv.x; acc[1] += a * bv.y; acc[2] += a * bv.z; acc[3] += a * bv.w;
    }
    __syncthreads();
    *(float4*)(Bf + row * 68 + col4) = make_float4(acc[0], acc[1], acc[2], acc[3]);
    for (int idx = t; idx < 4096; idx += 1024) A[(idx & 63) * 68 + (idx >> 6)] = pw[idx];
    __syncthreads();
    if (t < 64) {
        float a2 = 0.f;
#pragma unroll 16
        for (int e = 0; e < 64; e++) a2 += A[e * 68 + t] * s_sx[e];
        s_psx[t] = a2;
    }
    acc[0] = acc[1] = acc[2] = acc[3] = 0.f;
#pragma unroll 8
    for (int e = 0; e < 64; e++) {
        float a = A[e * 68 + row];
        float4 bv = *(const float4*)(Bf + e * 68 + col4);
        acc[0] += a * bv.x; acc[1] += a * bv.y; acc[2] += a * bv.z; acc[3] += a * bv.w;
    }
    __syncthreads();
    {
        int c = row;
#pragma unroll
        for (int j = 0; j < 4; j++) {
            int d = col4 + j;
            Bf[c*68+d] = acc[j] + s_pb[c]*(s_tsx[d] + 65536.f*s_tb[d]) + s_psx[c]*s_tb[d];
        }
    }
    __syncthreads();
    {
        const int w = t >> 5, lane = t & 31;
        for (int c = w*2; c < w*2+2; c++) {
            float v0 = Bf[c*68+lane], v1 = Bf[c*68+32+lane];
            float m = fmaxf(v0, v1);
#pragma unroll
            for (int o = 16; o >= 1; o >>= 1) m = fmaxf(m, __shfl_xor_sync(0xffffffffu, m, o));
            float e0 = __expf(v0-m), e1 = __expf(v1-m), s = e0+e1;
#pragma unroll
            for (int o = 16; o >= 1; o >>= 1) s += __shfl_xor_sync(0xffffffffu, s, o);
            float inv = 1.f/s;
            A[lane*68+c] = e0*inv;
            A[(lane+32)*68+c] = e1*inv;
        }
    }
    __syncthreads();
    for (int idx = t; idx < 4096; idx += 1024) Bf[(idx >> 6) * 68 + (idx & 63)] = gw[idx];
    __syncthreads();
    if (t < 64) {
        float bs = 0.f;
#pragma unroll 16
        for (int d = 0; d < 64; d++) bs += A[d*68+t]*s_gb[d];
        g_beta[b*64+t] = bs;
    }
    acc[0] = acc[1] = acc[2] = acc[3] = 0.f;
#pragma unroll 8
    for (int d = 0; d < 64; d++) {
        float a = A[d * 68 + row];
        float4 bv = *(const float4*)(Bf + d * 68 + col4);
        acc[0] += a * bv.x; acc[1] += a * bv.y; acc[2] += a * bv.z; acc[3] += a * bv.w;
    }
    *(float4*)(g_R + b * 4096 + row * 64 + col4) = make_float4(acc[0], acc[1], acc[2], acc[3]);
    if (b == 0 && t < 64) {
        float s = 0.f;
        const float4* wr = (const float4*)(ww + t * 64);
#pragma unroll
        for (int k = 0; k < 16; k++) {
            float4 v = wr[k];
            s += v.x + v.y + v.z + v.w;
        }
        g_Sw[t] = s;
    }
}

// wy = R*T + bias via bf16 m16n8k16; write bf16 wy; BN stats from fp32 accum.
__global__ __launch_bounds__(256) void kB(const float* __restrict__ wbias) {
    __shared__ __align__(16) __nv_bfloat16 As[64 * 72];
    __shared__ __align__(16) float Ds[64 * 68];
    __shared__ float sb[64];
    const int oc = blockIdx.x, b = blockIdx.y, bz = blockIdx.z, t = threadIdx.x;
    const int w = t >> 5, lane = t & 31, gid = lane >> 2, tig = lane & 3;
    const int cs = w & 3, jh = w >> 2;
    if (t < 64) sb[t] = g_beta[b * 64 + t];
    const float swv = g_Sw[oc], wbv = wbias[oc];
    const float* Rb = g_R + b * 4096;
    const int r = cs * 16 + gid;
    unsigned ar[4][4];
#pragma unroll
    for (int s = 0; s < 4; s++) {
        int c = 16 * s + 2 * tig;
        ar[s][0] = bpk(Rb[r * 64 + c],           Rb[r * 64 + c + 1]);
        ar[s][1] = bpk(Rb[(r + 8) * 64 + c],     Rb[(r + 8) * 64 + c + 1]);
        ar[s][2] = bpk(Rb[r * 64 + c + 8],       Rb[r * 64 + c + 9]);
        ar[s][3] = bpk(Rb[(r + 8) * 64 + c + 8], Rb[(r + 8) * 64 + c + 9]);
    }
    const __nv_bfloat16* Tb = g_T + ((long)(b * 64 + oc)) * 65536;
    __nv_bfloat16* Wb = g_W + ((long)(b * 64 + oc)) * 65536;
    const unsigned short* Au = (const unsigned short*)As;
    float ls = 0.f, lq = 0.f;
    const int e = t >> 2, q4 = t & 3;
    __syncthreads();
    for (int jt = bz * 4; jt < bz * 4 + 4; jt++) {
        int j0 = jt * 64;
        { // stage 64x64 bf16 tile raw (no widening)
            const uint2* s2p = (const uint2*)(Tb + e * 1024 + j0 + q4 * 16);
            uint2* d2 = (uint2*)(As + e * 72 + q4 * 16);
            d2[0] = s2p[0]; d2[1] = s2p[1]; d2[2] = s2p[2]; d2[3] = s2p[3];
        }
        __syncthreads();
#pragma unroll
        for (int nt = 0; nt < 4; nt++) {
            float acc[4] = {0.f, 0.f, 0.f, 0.f};
            int jb = jh * 32 + nt * 8;
#pragma unroll
            for (int s = 0; s < 4; s++) {
                int r0 = 16 * s + 2 * tig;
                int col = jb + gid;
                unsigned bb[2];
                bb[0] = (unsigned)Au[r0 * 72 + col] |
                        ((unsigned)Au[(r0 + 1) * 72 + col] << 16);
                bb[1] = (unsigned)Au[(r0 + 8) * 72 + col] |
                        ((unsigned)Au[(r0 + 9) * 72 + col] << 16);
                mma16(acc, ar[s], bb);
            }
            int c0 = cs * 16 + gid, jj = jb + 2 * tig;
            float bias0 = sb[c0] * swv + wbv, bias1 = sb[c0 + 8] * swv + wbv;
            Ds[jj * 68 + c0] = acc[0] + bias0;
            Ds[(jj + 1) * 68 + c0] = acc[1] + bias0;
            Ds[jj * 68 + c0 + 8] = acc[2] + bias1;
            Ds[(jj + 1) * 68 + c0 + 8] = acc[3] + bias1;
        }
        __syncthreads();
        {
            int j = t >> 2, h = t & 3;
#pragma unroll
            for (int kk = 0; kk < 4; kk++) {
                float4 v = *(const float4*)(Ds + j * 68 + h * 16 + 4 * kk);
                ls += v.x + v.y + v.z + v.w;
                lq += v.x * v.x + v.y * v.y + v.z * v.z + v.w * v.w;
                uint2 pk2;
                pk2.x = bpk(v.x, v.y);
                pk2.y = bpk(v.z, v.w);
                *(uint2*)(Wb + (j0 + j) * 64 + h * 16 + 4 * kk) = pk2;
            }
        }
        __syncthreads();
    }
#pragma unroll
    for (int o = 16; o >= 1; o >>= 1) {
        ls += __shfl_xor_sync(0xffffffffu, ls, o);
        lq += __shfl_xor_sync(0xffffffffu, lq, o);
    }
    if (lane == 0) { atomicAdd(&g_sum[oc], ls); atomicAdd(&g_sumsq[oc], lq); }
}

// BN apply + residual from bf16 wy; scale/shift inline.
__global__ __launch_bounds__(256) void k5(const float* __restrict__ x,
                                          const float* __restrict__ gamma,
                                          const float* __restrict__ bnb,
                                          float* __restrict__ out) {
    long i4 = (long)blockIdx.x * 256 + threadIdx.x;
    int ch = (int)(i4 >> 14) & 63;
    float m = __ldg(&g_sum[ch]) * (1.f / CNT);
    float v = __ldg(&g_sumsq[ch]) * (1.f / CNT) - m * m;
    float sc = __ldg(&gamma[ch]) * rsqrtf(v + 1e-5f);
    float sh = __ldg(&bnb[ch]) - m * sc;
    uint2 wraw = *(const uint2*)(g_W + i4 * 4);
    float2 w0 = __bfloat1622float2(*(__nv_bfloat162*)&wraw.x);
    float2 w1 = __bfloat1622float2(*(__nv_bfloat162*)&wraw.y);
    float4 xv = ((const float4*)x)[i4];
    float4 o;
    o.x = w0.x * sc + sh + xv.x;
    o.y = w0.y * sc + sh + xv.y;
    o.z = w1.x * sc + sh + xv.z;
    o.w = w1.y * sc + sh + xv.w;
    ((float4*)out)[i4] = o;
}

extern "C" void kernel_launch(void* const* d_in, const int* in_sizes, int n_in,
                              void* d_out, int out_size) {
    const float* x  = (const float*)d_in[0];
    const float* tw = (const float*)d_in[1];
    const float* tb = (const float*)d_in[2];
    const float* pw = (const float*)d_in[3];
    const float* pb = (const float*)d_in[4];
    const float* gw = (const float*)d_in[5];
    const float* gb = (const float*)d_in[6];
    const float* ww = (const float*)d_in[7];
    const float* wb = (const float*)d_in[8];
    const float* gamma = (const float*)d_in[9];
    const float* bnb = (const float*)d_in[10];
    float* out = (float*)d_out;

    static cudaStream_t s2 = nullptr;
    static cudaEvent_t evA = nullptr, evB = nullptr;
    if (!s2) {
        int leastPrio = 0, greatestPrio = 0;
        cudaDeviceGetStreamPriorityRange(&leastPrio, &greatestPrio);
        cudaStreamCreateWithPriority(&s2, cudaStreamNonBlocking, leastPrio);
        cudaEventCreateWithFlags(&evA, cudaEventDisableTiming);
        cudaEventCreateWithFlags(&evB, cudaEventDisableTiming);
        cudaFuncSetAttribute(kG, cudaFuncAttributeMaxDynamicSharedMemorySize, 70000);
    }
    const int kg_smem = 2 * 64 * 132 * 4;

    k0<<<64, 256>>>();
    cudaEventRecord(evA, 0);
    cudaStreamWaitEvent(s2, evA, 0);
    kT<<<dim3(2, 256), 256, 0, s2>>>(x, ww);
    kG<<<dim3(128, 4), 256, kg_smem>>>(x);
    k2<<<4, 1024>>>(tw, tb, pw, pb, gw, gb, ww);
    cudaEventRecord(evB, s2);
    cudaStreamWaitEvent(0, evB, 0);
    kB<<<dim3(64, 4, 4), 256>>>(wb);
    k5<<<16384, 256>>>(x, gamma, bnb, out);
}